// round 1
// baseline (speedup 1.0000x reference)
#include <cuda_runtime.h>
#include <math.h>

#define C 150
#define D 128
#define GRID1 152
#define T1 512
#define NWARP 16
#define TILE 256
#define ACC_FLOATS (2*C*D)          // 38400
#define CNT_FLOATS (2*C)            // 300
#define SLAB (ACC_FLOATS + CNT_FLOATS)  // 38700
#define SLAB_PAD 38720
#define INV_TEMP 5.0f               // 1 / 0.2

// deterministic per-CTA partials (no FP atomics anywhere)
__device__ float g_partial[GRID1 * SLAB_PAD];   // ~23.5 MB
__device__ float g_ab[2 * C * D];               // normalized means (A then B)
__device__ float g_logits[C * C];

// ---------------------------------------------------------------------------
// K1: segmented group sums. Warp w exclusively owns (group = w>>3, class&7 = w&7)
// so SMEM accumulation is race-free without atomics.
// ---------------------------------------------------------------------------
__global__ __launch_bounds__(T1, 1)
void k1_accumulate(const float* __restrict__ pred,
                   const int*   __restrict__ mask,
                   const int*   __restrict__ seg,
                   const int*   __restrict__ grp,
                   int N)
{
    extern __shared__ float smem[];
    float*    sacc  = smem;                         // [2][C][D]
    float*    scnt  = smem + ACC_FLOATS;            // [2][C]
    unsigned* slist = (unsigned*)(smem + SLAB);     // [NWARP][TILE]

    const int tid = threadIdx.x;
    for (int i = tid; i < SLAB; i += T1) smem[i] = 0.0f;
    __syncthreads();

    const int chunk = (N + GRID1 - 1) / GRID1;
    const int start = blockIdx.x * chunk;
    const int end   = min(N, start + chunk);

    const int wid  = tid >> 5;
    const int lane = tid & 31;
    const int gown = wid >> 3;     // group this warp owns (0/1)
    const int mown = wid & 7;      // class mod-8 this warp owns

    unsigned* mylist = slist + wid * TILE;
    float*    myacc  = sacc + gown * (C * D);
    float*    mycnt  = scnt + gown * C;

    for (int tbase = start; tbase < end; tbase += TILE) {
        const int tend = min(end, tbase + TILE);

        // ---- phase A: scan metadata, compact matched indices into SMEM list
        int cnt = 0;
        for (int base = tbase; base < tend; base += 32) {
            const int idx = base + lane;
            const bool inb = idx < tend;
            const int sv = inb ? seg[idx]  : -1;
            const int mk = inb ? mask[idx] : 0;
            const int gv = inb ? grp[idx]  : -1;
            const bool valid = (mk > 0) && (sv != -1);
            const int sc = min(max(sv, 0), C - 1);
            const bool match = valid && (gv == gown) && ((sc & 7) == mown);
            const unsigned bal = __ballot_sync(0xffffffffu, match);
            if (match) {
                const int pos = cnt + __popc(bal & ((1u << lane) - 1u));
                mylist[pos] = ((unsigned)idx << 8) | (unsigned)sc;
            }
            cnt += __popc(bal);
        }
        __syncwarp();

        // ---- phase B: drain list with 8-deep LDG.128 prefetch
        for (int j = 0; j < cnt; j += 8) {
            const int m = min(8, cnt - j);
            unsigned e[8];
            float4   v[8];
            #pragma unroll
            for (int u = 0; u < 8; u++) {
                if (u < m) {
                    e[u] = mylist[j + u];
                    const float* src = pred + (size_t)(e[u] >> 8) * D + lane * 4;
                    v[u] = *(const float4*)src;
                }
            }
            #pragma unroll
            for (int u = 0; u < 8; u++) {
                if (u < m) {
                    const int sc = (int)(e[u] & 255u);
                    float* arow = myacc + sc * D + lane * 4;
                    float4 a = *(float4*)arow;
                    a.x += v[u].x; a.y += v[u].y; a.z += v[u].z; a.w += v[u].w;
                    *(float4*)arow = a;
                    if (lane == 0) mycnt[sc] += 1.0f;
                }
            }
        }
        __syncwarp();
    }
    __syncthreads();

    // flush full slab (deterministic reduction in K2)
    float* out = g_partial + (size_t)blockIdx.x * SLAB_PAD;
    for (int i = tid; i < SLAB; i += T1) out[i] = smem[i];
}

// ---------------------------------------------------------------------------
// K2: reduce partials -> mean -> L2 normalize.  grid = 2*C blocks, D threads.
// ---------------------------------------------------------------------------
__global__ void k2_mean_norm()
{
    const int g = blockIdx.x / C;
    const int c = blockIdx.x % C;
    const int d = threadIdx.x;   // 0..127
    __shared__ float red[D];

    // reduce count
    float pc = 0.0f;
    for (int k = d; k < GRID1; k += D)
        pc += g_partial[(size_t)k * SLAB_PAD + ACC_FLOATS + g * C + c];
    red[d] = pc; __syncthreads();
    for (int s = 64; s > 0; s >>= 1) { if (d < s) red[d] += red[d + s]; __syncthreads(); }
    const float cnt = fmaxf(red[0], 1.0f);
    __syncthreads();

    // reduce vector sum
    const int off = (g * C + c) * D + d;
    float s = 0.0f;
    for (int k = 0; k < GRID1; k++)
        s += g_partial[(size_t)k * SLAB_PAD + off];
    const float mean = s / cnt;

    // L2 norm
    red[d] = mean * mean; __syncthreads();
    for (int s2 = 64; s2 > 0; s2 >>= 1) { if (d < s2) red[d] += red[d + s2]; __syncthreads(); }
    const float nrm = sqrtf(red[0]);

    g_ab[off] = mean / nrm;
}

// ---------------------------------------------------------------------------
// K3: logits[i][j] = dot(a[i], b[j]) / T.  grid = C blocks, 256 threads.
// B is transposed in SMEM with pad-152 stride (conflict-free).
// ---------------------------------------------------------------------------
__global__ void k3_logits()
{
    extern __shared__ float sm[];
    float* bsm  = sm;              // [D][152]
    float* arow = sm + D * 152;    // [D]
    const int i = blockIdx.x;
    const int tid = threadIdx.x;

    for (int idx = tid; idx < C * D; idx += 256) {
        const int c = idx >> 7, d = idx & 127;
        bsm[d * 152 + c] = g_ab[C * D + idx];
    }
    if (tid < D) arow[tid] = g_ab[i * D + tid];
    __syncthreads();

    if (tid < C) {
        float acc = 0.0f;
        #pragma unroll 8
        for (int k = 0; k < D; k++)
            acc += arow[k] * bsm[k * 152 + tid];
        g_logits[i * C + tid] = acc * INV_TEMP;
    }
}

// ---------------------------------------------------------------------------
// K4: symmetric InfoNCE scalar.  one block, 256 threads.
// ---------------------------------------------------------------------------
__global__ void k4_loss(float* __restrict__ out)
{
    __shared__ float red[256];
    const int tid = threadIdx.x;
    float contrib = 0.0f;

    if (tid < C) {
        const int r = tid;
        const float diag = g_logits[r * C + r];

        float mr = -1e30f;
        for (int j = 0; j < C; j++) mr = fmaxf(mr, g_logits[r * C + j]);
        float sr = 0.0f;
        for (int j = 0; j < C; j++) sr += expf(g_logits[r * C + j] - mr);
        const float rowlse = mr + logf(sr);

        float mc = -1e30f;
        for (int j = 0; j < C; j++) mc = fmaxf(mc, g_logits[j * C + r]);
        float sc = 0.0f;
        for (int j = 0; j < C; j++) sc += expf(g_logits[j * C + r] - mc);
        const float collse = mc + logf(sc);

        contrib = (rowlse - diag) + (collse - diag);
    }
    red[tid] = contrib; __syncthreads();
    for (int s = 128; s > 0; s >>= 1) { if (tid < s) red[tid] += red[tid + s]; __syncthreads(); }
    if (tid == 0) out[0] = red[0] / (2.0f * C);   // ((Σrow + Σcol)/C) / 2
}

// ---------------------------------------------------------------------------
extern "C" void kernel_launch(void* const* d_in, const int* in_sizes, int n_in,
                              void* d_out, int out_size)
{
    const float* pred = (const float*)d_in[0];
    // d_in[1] = target (unused by the loss math)
    const int* mask = (const int*)d_in[2];
    const int* seg  = (const int*)d_in[3];
    const int* grp  = (const int*)d_in[4];
    const int N = in_sizes[2];

    const size_t smem1 = SLAB * sizeof(float) + NWARP * TILE * sizeof(unsigned);
    cudaFuncSetAttribute(k1_accumulate, cudaFuncAttributeMaxDynamicSharedMemorySize, (int)smem1);
    const size_t smem3 = (D * 152 + D) * sizeof(float);
    cudaFuncSetAttribute(k3_logits, cudaFuncAttributeMaxDynamicSharedMemorySize, (int)smem3);

    k1_accumulate<<<GRID1, T1, smem1>>>(pred, mask, seg, grp, N);
    k2_mean_norm<<<2 * C, D>>>();
    k3_logits<<<C, 256, smem3>>>();
    k4_loss<<<1, 256>>>((float*)d_out);
}

// round 2
// speedup vs baseline: 1.3715x; 1.3715x over previous
#include <cuda_runtime.h>
#include <math.h>

#define C 150
#define D 128
#define NCHUNK 19
#define NSLICE 8
#define COLS 16              // columns per CTA slice
#define NB0 304              // K0 blocks
#define SKIPC 0xFFFFu
#define NMAX 2097152
#define WACC_F (2*C*COLS)    // 4800 floats per-warp accumulator
#define INV_TEMP 5.0f

// ---- device scratch (all fully re-written every launch; no cross-replay state) ----
__device__ unsigned short g_codes[NMAX];          // 4 MB   bucket code per point (or SKIPC)
__device__ int            g_cntpart[NB0 * 2 * C]; // per-K0-block integer histograms
__device__ float          g_part1[NSLICE * NCHUNK * WACC_F]; // 2.9 MB CTA partial sums
__device__ float          g_ab[2 * C * D];        // normalized means (A then B)
__device__ float          g_contrib[C];           // per-class symmetric-NCE contribution

// ---------------------------------------------------------------------------
// K0: encode metadata -> u16 codes (read 24MB once) + deterministic int counts.
// ---------------------------------------------------------------------------
__global__ __launch_bounds__(256)
void k0_encode(const int* __restrict__ mask, const int* __restrict__ seg,
               const int* __restrict__ grp, int N, int NPAD)
{
    __shared__ int hist[2 * C];
    for (int i = threadIdx.x; i < 2 * C; i += 256) hist[i] = 0;
    __syncthreads();

    const int pairs = NPAD >> 1;
    for (int p = blockIdx.x * 256 + threadIdx.x; p < pairs; p += NB0 * 256) {
        const int i0 = 2 * p;
        unsigned c0 = SKIPC, c1 = SKIPC;
        if (i0 + 1 < N) {
            int2 m = *(const int2*)(mask + i0);
            int2 s = *(const int2*)(seg  + i0);
            int2 g = *(const int2*)(grp  + i0);
            if (m.x > 0 && s.x != -1 && (unsigned)g.x <= 1u)
                c0 = (unsigned)g.x * C + (unsigned)min(max(s.x, 0), C - 1);
            if (m.y > 0 && s.y != -1 && (unsigned)g.y <= 1u)
                c1 = (unsigned)g.y * C + (unsigned)min(max(s.y, 0), C - 1);
        } else if (i0 < N) {
            int m = mask[i0], s = seg[i0], g = grp[i0];
            if (m > 0 && s != -1 && (unsigned)g <= 1u)
                c0 = (unsigned)g * C + (unsigned)min(max(s, 0), C - 1);
        }
        if (c0 < 2 * C) atomicAdd(&hist[c0], 1);
        if (c1 < 2 * C) atomicAdd(&hist[c1], 1);
        ((unsigned*)g_codes)[p] = c0 | (c1 << 16);
    }
    __syncthreads();
    for (int i = threadIdx.x; i < 2 * C; i += 256)
        g_cntpart[blockIdx.x * 2 * C + i] = hist[i];
}

// ---------------------------------------------------------------------------
// K1: column-sliced segmented sums. grid = NSLICE*NCHUNK CTAs, 256 threads.
// Per-warp private SMEM accumulator -> race-free, deterministic, no atomics.
// Double-buffered 32-deep LDG batches keep DRAM latency covered.
// ---------------------------------------------------------------------------
__global__ __launch_bounds__(256, 1)
void k1_accumulate(const float* __restrict__ pred, int N, int chTiles)
{
    extern __shared__ float sm[];
    const int tid  = threadIdx.x;
    const int wid  = tid >> 5;
    const int lane = tid & 31;
    const int half = lane >> 4;       // 0: even point of pair, 1: odd point
    const int cj   = lane & 15;       // column within slice
    float* wacc = sm + wid * WACC_F;

    for (int i = tid; i < 8 * WACC_F; i += 256) sm[i] = 0.0f;
    __syncthreads();

    const int slice   = blockIdx.x / NCHUNK;
    const int chunk   = blockIdx.x % NCHUNK;
    const int colbase = slice * COLS;
    const unsigned* codes32 = (const unsigned*)g_codes;

    auto loadtile = [&](int tt, float* v, unsigned& pk) {
        const int base = (chunk * chTiles + tt) * 64;
        pk = codes32[(base >> 1) + lane];
        if (base + 64 <= N) {
            const float* p = pred + (size_t)(base + half) * D + colbase + cj;
            #pragma unroll
            for (int u = 0; u < 32; u++) v[u] = p[(size_t)u * (2 * D)];
        } else {
            #pragma unroll
            for (int u = 0; u < 32; u++) {
                int idx = base + 2 * u + half;
                idx = idx < N ? idx : N - 1;          // clamp; code is SKIPC for OOB
                v[u] = pred[(size_t)idx * D + colbase + cj];
            }
        }
    };
    auto accum = [&](const float* v, unsigned pk) {
        #pragma unroll
        for (int u = 0; u < 32; u++) {
            const unsigned pp = __shfl_sync(0xffffffffu, pk, u);
            const unsigned bc = half ? (pp >> 16) : (pp & 0xffffu);
            if (bc < 2 * C) wacc[bc * COLS + cj] += v[u];
        }
    };

    float va[32], vb[32];
    unsigned pka, pkb;
    int t = wid;
    if (t < chTiles) {
        loadtile(t, va, pka);
        while (true) {
            int tn = t + 8;
            if (tn < chTiles) {
                loadtile(tn, vb, pkb);
                accum(va, pka);
                int tnn = tn + 8;
                if (tnn < chTiles) {
                    loadtile(tnn, va, pka);
                    accum(vb, pkb);
                    t = tnn;
                } else { accum(vb, pkb); break; }
            } else { accum(va, pka); break; }
        }
    }
    __syncthreads();

    // reduce 8 warp slabs -> one CTA partial slab (deterministic order)
    for (int i = tid; i < WACC_F; i += 256) {
        float s = 0.0f;
        #pragma unroll
        for (int w = 0; w < 8; w++) s += sm[w * WACC_F + i];
        g_part1[(size_t)blockIdx.x * WACC_F + i] = s;
    }
}

// ---------------------------------------------------------------------------
// K2: reduce partials -> mean -> L2 normalize. grid = 2*C blocks, 128 threads.
// ---------------------------------------------------------------------------
__global__ void k2_mean_norm()
{
    __shared__ float red[D];
    const int gc = blockIdx.x;     // g*C + c
    const int d  = threadIdx.x;    // column 0..127

    float pc = 0.0f;
    for (int b = d; b < NB0; b += D) pc += (float)g_cntpart[b * 2 * C + gc];
    red[d] = pc; __syncthreads();
    for (int s = 64; s > 0; s >>= 1) { if (d < s) red[d] += red[d + s]; __syncthreads(); }
    const float cnt = fmaxf(red[0], 1.0f);
    __syncthreads();

    const int cs = d >> 4, j = d & 15;   // slice, col-in-slice (col == d)
    float s = 0.0f;
    #pragma unroll
    for (int h = 0; h < NCHUNK; h++)
        s += g_part1[(size_t)(cs * NCHUNK + h) * WACC_F + gc * COLS + j];
    const float mean = s / cnt;

    red[d] = mean * mean; __syncthreads();
    for (int s2 = 64; s2 > 0; s2 >>= 1) { if (d < s2) red[d] += red[d + s2]; __syncthreads(); }
    const float inv = rsqrtf(red[0]);

    g_ab[gc * D + d] = mean * inv;
}

// ---------------------------------------------------------------------------
// K3: block i computes logits row i AND column i, then both logsumexps.
// grid = C blocks, 256 threads. B/A transposed in padded SMEM (conflict-free).
// ---------------------------------------------------------------------------
__global__ void k3_lse()
{
    extern __shared__ float s3[];
    float* aT  = s3;                 // [D][152]
    float* bT  = aT + D * 152;       // [D][152]
    float* ai  = bT + D * 152;       // [D]
    float* bi  = ai + D;             // [D]
    float* red = bi + D;             // [256]
    __shared__ float diag_s;

    const int i = blockIdx.x, tid = threadIdx.x;

    for (int idx = tid; idx < C * D; idx += 256) {
        const int c = idx >> 7, d = idx & 127;
        aT[d * 152 + c] = g_ab[idx];
        bT[d * 152 + c] = g_ab[C * D + idx];
    }
    if (tid < D) { ai[tid] = g_ab[i * D + tid]; bi[tid] = g_ab[C * D + i * D + tid]; }
    __syncthreads();

    float x = -1e30f, y = -1e30f;
    if (tid < C) {
        float xs = 0.0f, ys = 0.0f;
        #pragma unroll 8
        for (int k = 0; k < D; k++) {
            xs += ai[k] * bT[k * 152 + tid];   // logits[i][tid]
            ys += bi[k] * aT[k * 152 + tid];   // logits[tid][i]
        }
        x = xs * INV_TEMP; y = ys * INV_TEMP;
    }
    if (tid == i) diag_s = x;

    // row logsumexp
    red[tid] = x; __syncthreads();
    for (int s = 128; s > 0; s >>= 1) { if (tid < s) red[tid] = fmaxf(red[tid], red[tid + s]); __syncthreads(); }
    const float mx = red[0]; __syncthreads();
    red[tid] = (tid < C) ? expf(x - mx) : 0.0f; __syncthreads();
    for (int s = 128; s > 0; s >>= 1) { if (tid < s) red[tid] += red[tid + s]; __syncthreads(); }
    const float rowlse = mx + logf(red[0]); __syncthreads();

    // col logsumexp
    red[tid] = y; __syncthreads();
    for (int s = 128; s > 0; s >>= 1) { if (tid < s) red[tid] = fmaxf(red[tid], red[tid + s]); __syncthreads(); }
    const float my = red[0]; __syncthreads();
    red[tid] = (tid < C) ? expf(y - my) : 0.0f; __syncthreads();
    for (int s = 128; s > 0; s >>= 1) { if (tid < s) red[tid] += red[tid + s]; __syncthreads(); }
    const float collse = my + logf(red[0]);

    if (tid == 0) g_contrib[i] = (rowlse - diag_s) + (collse - diag_s);
}

// ---------------------------------------------------------------------------
// K4: final scalar. 1 block, 256 threads.
// ---------------------------------------------------------------------------
__global__ void k4_final(float* __restrict__ out)
{
    __shared__ float red[256];
    const int tid = threadIdx.x;
    red[tid] = (tid < C) ? g_contrib[tid] : 0.0f; __syncthreads();
    for (int s = 128; s > 0; s >>= 1) { if (tid < s) red[tid] += red[tid + s]; __syncthreads(); }
    if (tid == 0) out[0] = red[0] * (1.0f / (2.0f * C));
}

// ---------------------------------------------------------------------------
extern "C" void kernel_launch(void* const* d_in, const int* in_sizes, int n_in,
                              void* d_out, int out_size)
{
    const float* pred = (const float*)d_in[0];
    // d_in[1] = target (unused by the loss math)
    const int* mask = (const int*)d_in[2];
    const int* seg  = (const int*)d_in[3];
    const int* grp  = (const int*)d_in[4];
    const int N = in_sizes[2];

    const int totTiles = (N + 63) / 64;
    const int chTiles  = (totTiles + NCHUNK - 1) / NCHUNK;
    const int NPAD     = NCHUNK * chTiles * 64;   // <= NMAX for N <= ~2.09M

    const size_t smem1 = 8 * WACC_F * sizeof(float);               // 153.6 KB
    cudaFuncSetAttribute(k1_accumulate, cudaFuncAttributeMaxDynamicSharedMemorySize, (int)smem1);
    const size_t smem3 = (2 * D * 152 + 2 * D + 256) * sizeof(float);
    cudaFuncSetAttribute(k3_lse, cudaFuncAttributeMaxDynamicSharedMemorySize, (int)smem3);

    k0_encode<<<NB0, 256>>>(mask, seg, grp, N, NPAD);
    k1_accumulate<<<NSLICE * NCHUNK, 256, smem1>>>(pred, N, chTiles);
    k2_mean_norm<<<2 * C, D>>>();
    k3_lse<<<C, 256, smem3>>>();
    k4_final<<<1, 256>>>((float*)d_out);
}